// round 10
// baseline (speedup 1.0000x reference)
#include <cuda_runtime.h>
#include <cstdint>

#define NN 50000
#define EE 500000
#define DD 128
#define HH 128
#define RR 3
#define NBKT 1024   // MSD buckets (top 10 bits)

// ---------------- device scratch (static, no runtime alloc) ----------------
__device__ float g_xpos[NN * DD];
__device__ float g_xneg[NN * DD];
__device__ int g_inv[RR][NN];                       // inverse of final permutation
// MSD bucket machinery, per round x relation
__device__ unsigned g_key[2][RR][NN];
__device__ unsigned long long g_pairs[2][RR][NN];   // (key<<32)|idx
__device__ int g_arg[2][RR][NN];                    // argsort result per round
__device__ int g_bhist[2][RR][NBKT];
__device__ int g_bfill[2][RR][NBKT];
__device__ int g_bstart[2][RR][NBKT + 1];
// CSR
__device__ int g_deg[RR][NN];
__device__ int g_fill[RR][NN];
__device__ int g_rowptr[RR][NN + 1];
__device__ int g_col[RR][EE];
__device__ unsigned g_bs[RR][64];
__device__ unsigned g_bo[RR][64];

// ---------------- JAX threefry2x32 (exact, 20 rounds) ----------------
__host__ __device__ __forceinline__ void tf2x32(unsigned k0, unsigned k1,
                                                unsigned x0, unsigned x1,
                                                unsigned& o0, unsigned& o1) {
    unsigned ks0 = k0, ks1 = k1, ks2 = k0 ^ k1 ^ 0x1BD11BDAu;
    x0 += ks0; x1 += ks1;
#define TFR(r) { x0 += x1; x1 = (x1 << (r)) | (x1 >> (32 - (r))); x1 ^= x0; }
    TFR(13) TFR(15) TFR(26) TFR(6)   x0 += ks1; x1 += ks2 + 1u;
    TFR(17) TFR(29) TFR(16) TFR(24)  x0 += ks2; x1 += ks0 + 2u;
    TFR(13) TFR(15) TFR(26) TFR(6)   x0 += ks0; x1 += ks1 + 3u;
    TFR(17) TFR(29) TFR(16) TFR(24)  x0 += ks1; x1 += ks2 + 4u;
    TFR(13) TFR(15) TFR(26) TFR(6)   x0 += ks2; x1 += ks0 + 5u;
#undef TFR
    o0 = x0; o1 = x1;
}

// partitionable-mode random_bits: o0 ^ o1 of tf(key,(0,i))
__device__ __forceinline__ unsigned pbits(unsigned k0, unsigned k1, unsigned i) {
    unsigned o0, o1;
    tf2x32(k0, k1, 0u, i, o0, o1);
    return o0 ^ o1;
}

struct Keys12 { unsigned k[12]; };  // [round*6 + r*2 + {0,1}]

// ================= permutation machinery: MSD buckets + counting rank ==========
__global__ void bzero_kernel() {
    int i = blockIdx.x * blockDim.x + threadIdx.x;
    if (i < 2 * RR * NBKT) {
        ((int*)g_bhist)[i] = 0;
        ((int*)g_bfill)[i] = 0;
    }
}

__global__ void keyhist_kernel(Keys12 ks) {
    int r = blockIdx.y, round = blockIdx.z;
    int i = blockIdx.x * blockDim.x + threadIdx.x;
    if (i >= NN) return;
    unsigned k0 = ks.k[round * 6 + 2 * r], k1 = ks.k[round * 6 + 2 * r + 1];
    unsigned key = pbits(k0, k1, (unsigned)i);
    g_key[round][r][i] = key;
    atomicAdd(&g_bhist[round][r][key >> 22], 1);
}

__global__ void bprefix_kernel() {
    __shared__ unsigned s[NBKT];
    int r = blockIdx.x, round = blockIdx.y, tid = threadIdx.x;
    unsigned v = (unsigned)g_bhist[round][r][tid];
    s[tid] = v;
    __syncthreads();
    unsigned incl = v;
    for (int o = 1; o < NBKT; o <<= 1) {
        unsigned add = (tid >= o) ? s[tid - o] : 0u;
        __syncthreads();
        incl += add; s[tid] = incl;
        __syncthreads();
    }
    g_bstart[round][r][tid + 1] = (int)incl;
    if (tid == 0) g_bstart[round][r][0] = 0;
}

__global__ void bscatter_kernel() {
    int r = blockIdx.y, round = blockIdx.z;
    int i = blockIdx.x * blockDim.x + threadIdx.x;
    if (i >= NN) return;
    unsigned key = g_key[round][r][i];
    int b = (int)(key >> 22);
    int pos = g_bstart[round][r][b] + atomicAdd(&g_bfill[round][r][b], 1);
    g_pairs[round][r][pos] = ((unsigned long long)key << 32) | (unsigned)i;
}

__global__ void brank_kernel() {
    int gwarp = (blockIdx.x * blockDim.x + threadIdx.x) >> 5;
    int lane = threadIdx.x & 31;
    if (gwarp >= 2 * RR * NBKT) return;
    int round = gwarp / (RR * NBKT);
    int rem = gwarp - round * RR * NBKT;
    int r = rem >> 10, b = rem & (NBKT - 1);
    int base = g_bstart[round][r][b];
    int end = g_bstart[round][r][b + 1];
    int m = end - base;
    const unsigned long long* P = g_pairs[round][r];
    int* A = g_arg[round][r];
    for (int e = lane; e < m; e += 32) {
        unsigned long long me = P[base + e];
        int cnt = 0;
        for (int j = 0; j < m; j++) cnt += (P[base + j] < me) ? 1 : 0;
        A[base + cnt] = (int)(me & 0xffffffffu);
    }
}

__global__ void compose_invperm_kernel() {
    int r = blockIdx.y;
    int j = blockIdx.x * blockDim.x + threadIdx.x;
    if (j >= NN) return;
    int a2 = g_arg[1][r][j];
    int p = g_arg[0][r][a2];
    g_inv[r][p] = j;
}

// ================= CSR build =================
__global__ void csr_zero() {
    int i = blockIdx.x * blockDim.x + threadIdx.x;
    if (i < RR * NN) { ((int*)g_deg)[i] = 0; ((int*)g_fill)[i] = 0; }
}
__global__ void csr_hist(const int* __restrict__ ei) {
    int idx = blockIdx.x * blockDim.x + threadIdx.x;
    if (idx >= RR * EE) return;
    int r = idx / EE, e = idx - r * EE;
    int t = __ldg(ei + (size_t)r * 2 * EE + EE + e);
    atomicAdd(&g_deg[r][t], 1);
}
__global__ void scan1() {
    __shared__ unsigned s[1024];
    int r = blockIdx.y, b = blockIdx.x, tid = threadIdx.x;
    int i = b * 1024 + tid;
    unsigned v = (i < NN) ? (unsigned)g_deg[r][i] : 0u;
    s[tid] = v;
    __syncthreads();
    unsigned incl = v;
    for (int o = 1; o < 1024; o <<= 1) {
        unsigned add = (tid >= o) ? s[tid - o] : 0u;
        __syncthreads();
        incl += add; s[tid] = incl;
        __syncthreads();
    }
    if (i < NN) g_rowptr[r][i + 1] = (int)incl;
    if (tid == 1023) g_bs[r][b] = incl;
}
__global__ void scan2(int nb) {
    int r = blockIdx.x;
    if (threadIdx.x == 0) {
        unsigned run = 0;
        for (int b = 0; b < nb; b++) { unsigned t = g_bs[r][b]; g_bo[r][b] = run; run += t; }
    }
}
__global__ void scan3() {
    int r = blockIdx.y, b = blockIdx.x;
    int i = b * 1024 + threadIdx.x;
    if (i < NN) g_rowptr[r][i + 1] += (int)g_bo[r][b];
    if (b == 0 && threadIdx.x == 0) g_rowptr[r][0] = 0;
}
__global__ void csr_fill(const int* __restrict__ ei) {
    int idx = blockIdx.x * blockDim.x + threadIdx.x;
    if (idx >= RR * EE) return;
    int r = idx / EE, e = idx - r * EE;
    int s = __ldg(ei + (size_t)r * 2 * EE + e);
    int t = __ldg(ei + (size_t)r * 2 * EE + EE + e);
    int p = g_rowptr[r][t] + atomicAdd(&g_fill[r][t], 1);
    g_col[r][p] = s;
}

// ================= fused pos+neg dropout (+ permutation scatter) =================
__global__ void dropboth_kernel(const float* __restrict__ x, const int* __restrict__ inv,
                                unsigned kp0, unsigned kp1, unsigned kn0, unsigned kn1) {
    int i4 = blockIdx.x * blockDim.x + threadIdx.x;
    if (i4 >= NN * 32) return;
    int row = i4 >> 5, c = i4 & 31;
    float4 v = ((const float4*)x)[i4];
    unsigned base = (unsigned)i4 * 4u;
    float4 p, n;
    p.x = (pbits(kp0, kp1, base + 0u) & 0x80000000u) ? 0.f : 2.f * v.x;
    p.y = (pbits(kp0, kp1, base + 1u) & 0x80000000u) ? 0.f : 2.f * v.y;
    p.z = (pbits(kp0, kp1, base + 2u) & 0x80000000u) ? 0.f : 2.f * v.z;
    p.w = (pbits(kp0, kp1, base + 3u) & 0x80000000u) ? 0.f : 2.f * v.w;
    n.x = (pbits(kn0, kn1, base + 0u) & 0x80000000u) ? 0.f : 2.f * v.x;
    n.y = (pbits(kn0, kn1, base + 1u) & 0x80000000u) ? 0.f : 2.f * v.y;
    n.z = (pbits(kn0, kn1, base + 2u) & 0x80000000u) ? 0.f : 2.f * v.z;
    n.w = (pbits(kn0, kn1, base + 3u) & 0x80000000u) ? 0.f : 2.f * v.w;
    ((float4*)g_xpos)[i4] = p;
    ((float4*)g_xneg)[(size_t)inv[row] * 32 + c] = n;  // neg[i] = dropped(x)[perm[i]]
}

// ================= fused CSR-aggregate + mean + dual GEMM + bias + relu ============
// 128-row M tile, 512 threads, double-buffered W staging.
// smem: As[128][128] | Xs[128][128] | Ws[2][16][128]
__global__ void __launch_bounds__(512) agg_gemm_kernel(
        const float* __restrict__ xb, const int* __restrict__ rowptr,
        const int* __restrict__ colidx, const float* __restrict__ W1,
        const float* __restrict__ W2, const float* __restrict__ bias,
        float* __restrict__ O) {
    extern __shared__ float sm[];
    float* As = sm;                   // 16384 floats
    float* Xs = sm + 128 * 128;       // 16384 floats
    float* Ws = sm + 2 * 128 * 128;   // 2 * 2048 floats
    int tid = threadIdx.x, lane = tid & 31, w = tid >> 5;
    int m0 = blockIdx.x * 128;
    const float4* xb4 = (const float4*)xb;

    // load own x rows (128 rows x 32 float4s over 512 threads)
    float4* Xs4 = (float4*)Xs;
    for (int i = tid; i < 128 * 32; i += 512) {
        int rr = i >> 5, cc = i & 31, row = m0 + rr;
        Xs4[i] = (row < NN) ? xb4[(size_t)row * 32 + cc] : make_float4(0.f, 0.f, 0.f, 0.f);
    }
    // aggregate: warp per row, 8 rows per warp (16 warps x 8 = 128), mean folded in
    float4* As4 = (float4*)As;
    for (int j = 0; j < 8; j++) {
        int rr = w * 8 + j, row = m0 + rr;
        float4 acc = make_float4(0.f, 0.f, 0.f, 0.f);
        if (row < NN) {
            int beg = __ldg(rowptr + row), end = __ldg(rowptr + row + 1);
            int e = beg;
            for (; e + 4 <= end; e += 4) {
                int s0 = __ldg(colidx + e), s1 = __ldg(colidx + e + 1);
                int s2 = __ldg(colidx + e + 2), s3 = __ldg(colidx + e + 3);
                float4 v0 = xb4[(size_t)s0 * 32 + lane];
                float4 v1 = xb4[(size_t)s1 * 32 + lane];
                float4 v2 = xb4[(size_t)s2 * 32 + lane];
                float4 v3 = xb4[(size_t)s3 * 32 + lane];
                acc.x += v0.x + v1.x + v2.x + v3.x;
                acc.y += v0.y + v1.y + v2.y + v3.y;
                acc.z += v0.z + v1.z + v2.z + v3.z;
                acc.w += v0.w + v1.w + v2.w + v3.w;
            }
            for (; e < end; e++) {
                int s = __ldg(colidx + e);
                float4 v = xb4[(size_t)s * 32 + lane];
                acc.x += v.x; acc.y += v.y; acc.z += v.z; acc.w += v.w;
            }
            float inv = 1.f / fmaxf((float)(end - beg), 1.f);
            acc.x *= inv; acc.y *= inv; acc.z *= inv; acc.w *= inv;
        }
        As4[rr * 32 + lane] = acc;
    }

    // ---- unified GEMM over 16 k-tiles: t=0..7 As@W1, t=8..15 Xs@W2 ----
    float acc[8][4];
#pragma unroll
    for (int i = 0; i < 8; i++)
#pragma unroll
        for (int j = 0; j < 4; j++) acc[i][j] = 0.f;
    int tx = tid & 31, ty = tid >> 5;   // ty 0..15 -> rows ty*8..ty*8+7

    // stage tile 0 (W1, kt=0): 16x128 floats = 512 float4s, one per thread
    {
        int rrow = tid >> 5, rcol = (tid & 31) * 4;
        float4 wv = *(const float4*)(W1 + (size_t)rrow * HH + rcol);
        *(float4*)&Ws[(tid >> 5) * 128 + (tid & 31) * 4] = wv;
    }
    __syncthreads();  // also covers As/Xs writes above

#pragma unroll 1
    for (int t = 0; t < 16; t++) {
        const float* SRC = (t < 8) ? As : Xs;
        int kt = t & 7;
        float4 wvn;
        if (t < 15) {
            const float* Wn = (t + 1 < 8) ? W1 : W2;
            int ktn = (t + 1) & 7;
            wvn = *(const float4*)(Wn + (size_t)(ktn * 16 + (tid >> 5)) * HH + (tid & 31) * 4);
        }
        const float* WT = Ws + (t & 1) * 2048;
#pragma unroll
        for (int kk = 0; kk < 16; kk += 4) {
            float4 a4[8];
#pragma unroll
            for (int i = 0; i < 8; i++)
                a4[i] = *(const float4*)&SRC[(ty * 8 + i) * 128 + kt * 16 + kk];  // warp broadcast
#pragma unroll
            for (int j = 0; j < 4; j++) {
                float4 b = *(const float4*)&WT[(kk + j) * 128 + tx * 4];
#pragma unroll
                for (int i = 0; i < 8; i++) {
                    float a = (j == 0) ? a4[i].x : (j == 1) ? a4[i].y : (j == 2) ? a4[i].z : a4[i].w;
                    acc[i][0] += a * b.x;
                    acc[i][1] += a * b.y;
                    acc[i][2] += a * b.z;
                    acc[i][3] += a * b.w;
                }
            }
        }
        if (t < 15) {
            // write next tile into the other buffer (no reader conflicts), then barrier
            *(float4*)&Ws[((t + 1) & 1) * 2048 + (tid >> 5) * 128 + (tid & 31) * 4] = wvn;
            __syncthreads();
        }
    }

    float4 bb = *(const float4*)(bias + tx * 4);
#pragma unroll
    for (int i = 0; i < 8; i++) {
        int row = m0 + ty * 8 + i;
        if (row < NN) {
            float4 o;
            o.x = fmaxf(acc[i][0] + bb.x, 0.f);
            o.y = fmaxf(acc[i][1] + bb.y, 0.f);
            o.z = fmaxf(acc[i][2] + bb.z, 0.f);
            o.w = fmaxf(acc[i][3] + bb.w, 0.f);
            *(float4*)(O + (size_t)row * HH + tx * 4) = o;
        }
    }
}

// ---------------- host ----------------
extern "C" void kernel_launch(void* const* d_in, const int* in_sizes, int n_in,
                              void* d_out, int out_size) {
    const float* x = (const float*)d_in[0];
    const int* ei = (const int*)d_in[1];
    const float* Wl = (const float*)d_in[2];
    const float* bl = (const float*)d_in[3];
    const float* Wr = (const float*)d_in[4];
    float* out = (float*)d_out;
    (void)in_sizes; (void)n_in; (void)out_size;

    // ---- derive all JAX subkeys on host (partitionable semantics) ----
    unsigned kp[RR][2], kn[RR][2], s1k[RR][2], s2k[RR][2];
    for (int r = 0; r < RR; r++) {
        unsigned f0, f1;
        tf2x32(0u, 42u, 0u, (unsigned)r, f0, f1);           // fold_in
        tf2x32(f0, f1, 0u, 0u, kp[r][0], kp[r][1]);         // split[0]
        tf2x32(f0, f1, 0u, 1u, kn[r][0], kn[r][1]);         // split[1]
        unsigned pk0, pk1;
        tf2x32(f0, f1, 0u, 2u, pk0, pk1);                   // split[2] = kperm
        unsigned key10, key11;
        tf2x32(pk0, pk1, 0u, 0u, key10, key11);             // round1 new key
        tf2x32(pk0, pk1, 0u, 1u, s1k[r][0], s1k[r][1]);     // round1 use key
        tf2x32(key10, key11, 0u, 1u, s2k[r][0], s2k[r][1]); // round2 use key
    }

    // set attributes unconditionally every call (no static guards)
    cudaFuncSetAttribute(agg_gemm_kernel, cudaFuncAttributeMaxDynamicSharedMemorySize, 147456);

    void *p_xpos = nullptr, *p_xneg = nullptr, *p_inv = nullptr;
    void *p_rowptr = nullptr, *p_col = nullptr;
    cudaGetSymbolAddress(&p_xpos, g_xpos);
    cudaGetSymbolAddress(&p_xneg, g_xneg);
    cudaGetSymbolAddress(&p_inv, g_inv);
    cudaGetSymbolAddress(&p_rowptr, g_rowptr);
    cudaGetSymbolAddress(&p_col, g_col);
    float* xpos = (float*)p_xpos;
    float* xneg = (float*)p_xneg;
    int* invp = (int*)p_inv;
    int* rowptr = (int*)p_rowptr;
    int* colidx = (int*)p_col;

    // ---- CSR build (once per launch) ----
    const int NB = (NN + 1023) / 1024;  // 49
    csr_zero<<<(RR * NN + 255) / 256, 256>>>();
    csr_hist<<<(RR * EE + 255) / 256, 256>>>(ei);
    scan1<<<dim3(NB, RR), 1024>>>();
    scan2<<<RR, 32>>>(NB);
    scan3<<<dim3(NB, RR), 1024>>>();
    csr_fill<<<(RR * EE + 255) / 256, 256>>>(ei);

    // ---- permutations: MSD buckets + counting rank (both rounds concurrent) ----
    Keys12 KK;
    for (int r = 0; r < RR; r++) {
        KK.k[0 + 2 * r] = s1k[r][0]; KK.k[0 + 2 * r + 1] = s1k[r][1];
        KK.k[6 + 2 * r] = s2k[r][0]; KK.k[6 + 2 * r + 1] = s2k[r][1];
    }
    dim3 eg((NN + 255) / 256, RR, 2);
    bzero_kernel<<<(2 * RR * NBKT + 255) / 256, 256>>>();
    keyhist_kernel<<<eg, 256>>>(KK);
    bprefix_kernel<<<dim3(RR, 2), NBKT>>>();
    bscatter_kernel<<<eg, 256>>>();
    brank_kernel<<<(2 * RR * NBKT * 32 + 255) / 256, 256>>>();
    dim3 cg((NN + 255) / 256, RR);
    compose_invperm_kernel<<<cg, 256>>>();

    // ---- per-relation pipeline ----
    const int dropBlocks = (NN * 32 + 255) / 256;
    const int gemmBlocks = (NN + 127) / 128;
    for (int r = 0; r < RR; r++) {
        const float* W1 = Wl + (size_t)r * DD * HH;
        const float* W2 = Wr + (size_t)r * DD * HH;
        const float* bb = bl + (size_t)r * HH;
        dropboth_kernel<<<dropBlocks, 256>>>(x, invp + (size_t)r * NN,
                                             kp[r][0], kp[r][1], kn[r][0], kn[r][1]);
        agg_gemm_kernel<<<gemmBlocks, 512, 147456>>>(
            xpos, rowptr + (size_t)r * (NN + 1), colidx + (size_t)r * EE,
            W1, W2, bb, out + (size_t)r * NN * HH);
        agg_gemm_kernel<<<gemmBlocks, 512, 147456>>>(
            xneg, rowptr + (size_t)r * (NN + 1), colidx + (size_t)r * EE,
            W1, W2, bb, out + (size_t)(RR + r) * NN * HH);
    }
}

// round 11
// speedup vs baseline: 1.2252x; 1.2252x over previous
#include <cuda_runtime.h>
#include <cuda_bf16.h>
#include <cstdint>

#define NN 50000
#define EE 500000
#define DD 128
#define HH 128
#define RR 3
#define NBKT 1024   // MSD buckets (top 10 bits)

// ---------------- device scratch (static, no runtime alloc) ----------------
__device__ float g_xpos[NN * DD];
__device__ float g_xneg[NN * DD];
__device__ int g_inv[RR][NN];                       // inverse of final permutation
// MSD bucket machinery, per round x relation
__device__ unsigned g_key[2][RR][NN];
__device__ unsigned long long g_pairs[2][RR][NN];   // (key<<32)|idx
__device__ int g_arg[2][RR][NN];                    // argsort result per round
__device__ int g_bhist[2][RR][NBKT];
__device__ int g_bfill[2][RR][NBKT];
__device__ int g_bstart[2][RR][NBKT + 1];
// CSR
__device__ int g_deg[RR][NN];
__device__ int g_fill[RR][NN];
__device__ int g_rowptr[RR][NN + 1];
__device__ int g_col[RR][EE];
__device__ unsigned g_bs[RR][64];
__device__ unsigned g_bo[RR][64];
// pre-converted W: transposed [n][k], k=0..255 = [W1;W2], split hi/lo bf16
__device__ __nv_bfloat16 g_Wthi[RR][128 * 256];
__device__ __nv_bfloat16 g_Wtlo[RR][128 * 256];

// ---------------- JAX threefry2x32 (exact, 20 rounds) ----------------
__host__ __device__ __forceinline__ void tf2x32(unsigned k0, unsigned k1,
                                                unsigned x0, unsigned x1,
                                                unsigned& o0, unsigned& o1) {
    unsigned ks0 = k0, ks1 = k1, ks2 = k0 ^ k1 ^ 0x1BD11BDAu;
    x0 += ks0; x1 += ks1;
#define TFR(r) { x0 += x1; x1 = (x1 << (r)) | (x1 >> (32 - (r))); x1 ^= x0; }
    TFR(13) TFR(15) TFR(26) TFR(6)   x0 += ks1; x1 += ks2 + 1u;
    TFR(17) TFR(29) TFR(16) TFR(24)  x0 += ks2; x1 += ks0 + 2u;
    TFR(13) TFR(15) TFR(26) TFR(6)   x0 += ks0; x1 += ks1 + 3u;
    TFR(17) TFR(29) TFR(16) TFR(24)  x0 += ks1; x1 += ks2 + 4u;
    TFR(13) TFR(15) TFR(26) TFR(6)   x0 += ks2; x1 += ks0 + 5u;
#undef TFR
    o0 = x0; o1 = x1;
}

__device__ __forceinline__ unsigned pbits(unsigned k0, unsigned k1, unsigned i) {
    unsigned o0, o1;
    tf2x32(k0, k1, 0u, i, o0, o1);
    return o0 ^ o1;
}

struct Keys12 { unsigned k[12]; };  // [round*6 + r*2 + {0,1}]

// ================= permutation machinery: MSD buckets + counting rank ==========
__global__ void bzero_kernel() {
    int i = blockIdx.x * blockDim.x + threadIdx.x;
    if (i < 2 * RR * NBKT) {
        ((int*)g_bhist)[i] = 0;
        ((int*)g_bfill)[i] = 0;
    }
}

__global__ void keyhist_kernel(Keys12 ks) {
    int r = blockIdx.y, round = blockIdx.z;
    int i = blockIdx.x * blockDim.x + threadIdx.x;
    if (i >= NN) return;
    unsigned k0 = ks.k[round * 6 + 2 * r], k1 = ks.k[round * 6 + 2 * r + 1];
    unsigned key = pbits(k0, k1, (unsigned)i);
    g_key[round][r][i] = key;
    atomicAdd(&g_bhist[round][r][key >> 22], 1);
}

__global__ void bprefix_kernel() {
    __shared__ unsigned s[NBKT];
    int r = blockIdx.x, round = blockIdx.y, tid = threadIdx.x;
    unsigned v = (unsigned)g_bhist[round][r][tid];
    s[tid] = v;
    __syncthreads();
    unsigned incl = v;
    for (int o = 1; o < NBKT; o <<= 1) {
        unsigned add = (tid >= o) ? s[tid - o] : 0u;
        __syncthreads();
        incl += add; s[tid] = incl;
        __syncthreads();
    }
    g_bstart[round][r][tid + 1] = (int)incl;
    if (tid == 0) g_bstart[round][r][0] = 0;
}

__global__ void bscatter_kernel() {
    int r = blockIdx.y, round = blockIdx.z;
    int i = blockIdx.x * blockDim.x + threadIdx.x;
    if (i >= NN) return;
    unsigned key = g_key[round][r][i];
    int b = (int)(key >> 22);
    int pos = g_bstart[round][r][b] + atomicAdd(&g_bfill[round][r][b], 1);
    g_pairs[round][r][pos] = ((unsigned long long)key << 32) | (unsigned)i;
}

__global__ void brank_kernel() {
    int gwarp = (blockIdx.x * blockDim.x + threadIdx.x) >> 5;
    int lane = threadIdx.x & 31;
    if (gwarp >= 2 * RR * NBKT) return;
    int round = gwarp / (RR * NBKT);
    int rem = gwarp - round * RR * NBKT;
    int r = rem >> 10, b = rem & (NBKT - 1);
    int base = g_bstart[round][r][b];
    int end = g_bstart[round][r][b + 1];
    int m = end - base;
    const unsigned long long* P = g_pairs[round][r];
    int* A = g_arg[round][r];
    for (int e = lane; e < m; e += 32) {
        unsigned long long me = P[base + e];
        int cnt = 0;
        for (int j = 0; j < m; j++) cnt += (P[base + j] < me) ? 1 : 0;
        A[base + cnt] = (int)(me & 0xffffffffu);
    }
}

__global__ void compose_invperm_kernel() {
    int r = blockIdx.y;
    int j = blockIdx.x * blockDim.x + threadIdx.x;
    if (j >= NN) return;
    int a2 = g_arg[1][r][j];
    int p = g_arg[0][r][a2];
    g_inv[r][p] = j;
}

// ================= CSR build =================
__global__ void csr_zero() {
    int i = blockIdx.x * blockDim.x + threadIdx.x;
    if (i < RR * NN) { ((int*)g_deg)[i] = 0; ((int*)g_fill)[i] = 0; }
}
__global__ void csr_hist(const int* __restrict__ ei) {
    int idx = blockIdx.x * blockDim.x + threadIdx.x;
    if (idx >= RR * EE) return;
    int r = idx / EE, e = idx - r * EE;
    int t = __ldg(ei + (size_t)r * 2 * EE + EE + e);
    atomicAdd(&g_deg[r][t], 1);
}
__global__ void scan1() {
    __shared__ unsigned s[1024];
    int r = blockIdx.y, b = blockIdx.x, tid = threadIdx.x;
    int i = b * 1024 + tid;
    unsigned v = (i < NN) ? (unsigned)g_deg[r][i] : 0u;
    s[tid] = v;
    __syncthreads();
    unsigned incl = v;
    for (int o = 1; o < 1024; o <<= 1) {
        unsigned add = (tid >= o) ? s[tid - o] : 0u;
        __syncthreads();
        incl += add; s[tid] = incl;
        __syncthreads();
    }
    if (i < NN) g_rowptr[r][i + 1] = (int)incl;
    if (tid == 1023) g_bs[r][b] = incl;
}
__global__ void scan2(int nb) {
    int r = blockIdx.x;
    if (threadIdx.x == 0) {
        unsigned run = 0;
        for (int b = 0; b < nb; b++) { unsigned t = g_bs[r][b]; g_bo[r][b] = run; run += t; }
    }
}
__global__ void scan3() {
    int r = blockIdx.y, b = blockIdx.x;
    int i = b * 1024 + threadIdx.x;
    if (i < NN) g_rowptr[r][i + 1] += (int)g_bo[r][b];
    if (b == 0 && threadIdx.x == 0) g_rowptr[r][0] = 0;
}
__global__ void csr_fill(const int* __restrict__ ei) {
    int idx = blockIdx.x * blockDim.x + threadIdx.x;
    if (idx >= RR * EE) return;
    int r = idx / EE, e = idx - r * EE;
    int s = __ldg(ei + (size_t)r * 2 * EE + e);
    int t = __ldg(ei + (size_t)r * 2 * EE + EE + e);
    int p = g_rowptr[r][t] + atomicAdd(&g_fill[r][t], 1);
    g_col[r][p] = s;
}

// ================= W pre-convert: transpose + bf16 hi/lo split =================
__global__ void wconv_kernel(const float* __restrict__ Wl, const float* __restrict__ Wr) {
    int idx = blockIdx.x * blockDim.x + threadIdx.x;
    if (idx >= RR * 128 * 256) return;
    int r = idx / (128 * 256);
    int rem = idx - r * 128 * 256;
    int n = rem >> 8, k = rem & 255;
    float v = (k < DD) ? Wl[(size_t)r * DD * HH + (size_t)k * HH + n]
                       : Wr[(size_t)r * DD * HH + (size_t)(k - DD) * HH + n];
    __nv_bfloat16 hi = __float2bfloat16(v);
    __nv_bfloat16 lo = __float2bfloat16(v - __bfloat162float(hi));
    g_Wthi[r][n * 256 + k] = hi;
    g_Wtlo[r][n * 256 + k] = lo;
}

// ================= fused pos+neg dropout (+ permutation scatter) =================
__global__ void dropboth_kernel(const float* __restrict__ x, const int* __restrict__ inv,
                                unsigned kp0, unsigned kp1, unsigned kn0, unsigned kn1) {
    int i4 = blockIdx.x * blockDim.x + threadIdx.x;
    if (i4 >= NN * 32) return;
    int row = i4 >> 5, c = i4 & 31;
    float4 v = ((const float4*)x)[i4];
    unsigned base = (unsigned)i4 * 4u;
    float4 p, n;
    p.x = (pbits(kp0, kp1, base + 0u) & 0x80000000u) ? 0.f : 2.f * v.x;
    p.y = (pbits(kp0, kp1, base + 1u) & 0x80000000u) ? 0.f : 2.f * v.y;
    p.z = (pbits(kp0, kp1, base + 2u) & 0x80000000u) ? 0.f : 2.f * v.z;
    p.w = (pbits(kp0, kp1, base + 3u) & 0x80000000u) ? 0.f : 2.f * v.w;
    n.x = (pbits(kn0, kn1, base + 0u) & 0x80000000u) ? 0.f : 2.f * v.x;
    n.y = (pbits(kn0, kn1, base + 1u) & 0x80000000u) ? 0.f : 2.f * v.y;
    n.z = (pbits(kn0, kn1, base + 2u) & 0x80000000u) ? 0.f : 2.f * v.z;
    n.w = (pbits(kn0, kn1, base + 3u) & 0x80000000u) ? 0.f : 2.f * v.w;
    ((float4*)g_xpos)[i4] = p;
    ((float4*)g_xneg)[(size_t)inv[row] * 32 + c] = n;  // neg[i] = dropped(x)[perm[i]]
}

// ======== fused CSR-aggregate + mean + split-bf16 tensor-core dual GEMM ========
// 64-row M tile, 256 threads (8 warps). K=256 = [agg(128) | x(128)].
// acc = Ahi@Whi + Ahi@Wlo + Alo@Whi  (fp32 accumulate; al*wl ~2^-18 dropped)
// smem (bf16 elems): Ahi[64][264] | Alo[64][264] | Wshi[2][128][24] | Wslo[2][128][24]
#define A_STRIDE 264
#define AH_OFF 0
#define AL_OFF (64 * A_STRIDE)
#define WH_OFF (2 * 64 * A_STRIDE)
#define WL_OFF (WH_OFF + 2 * 128 * 24)
#define SMEM_ELEMS (WL_OFF + 2 * 128 * 24)   // 46080 bf16 = 92160 B

#define MMA_BF16(d, a, b0v, b1v) \
    asm volatile("mma.sync.aligned.m16n8k16.row.col.f32.bf16.bf16.f32 " \
        "{%0,%1,%2,%3}, {%4,%5,%6,%7}, {%8,%9}, {%0,%1,%2,%3};" \
        : "+f"(d[0]), "+f"(d[1]), "+f"(d[2]), "+f"(d[3]) \
        : "r"(a[0]), "r"(a[1]), "r"(a[2]), "r"(a[3]), "r"(b0v), "r"(b1v))

__global__ void __launch_bounds__(256) agg_gemm_kernel(
        const float* __restrict__ xb, const int* __restrict__ rowptr,
        const int* __restrict__ colidx,
        const __nv_bfloat16* __restrict__ WHg, const __nv_bfloat16* __restrict__ WLg,
        const float* __restrict__ bias, float* __restrict__ O) {
    extern __shared__ __nv_bfloat16 smb[];
    int tid = threadIdx.x, lane = tid & 31, w = tid >> 5;
    int m0 = blockIdx.x * 64;
    const float4* xb4 = (const float4*)xb;

    // ---- phase 1a: own x rows -> Alo/Ahi cols 128..255 ----
    for (int i = tid; i < 64 * 32; i += 256) {
        int rr = i >> 5, cc = i & 31, row = m0 + rr;
        float4 v = (row < NN) ? xb4[(size_t)row * 32 + cc] : make_float4(0.f, 0.f, 0.f, 0.f);
        int kcol = 128 + cc * 4;
        __nv_bfloat162 h01, h23, l01, l23;
        h01.x = __float2bfloat16(v.x); l01.x = __float2bfloat16(v.x - __bfloat162float(h01.x));
        h01.y = __float2bfloat16(v.y); l01.y = __float2bfloat16(v.y - __bfloat162float(h01.y));
        h23.x = __float2bfloat16(v.z); l23.x = __float2bfloat16(v.z - __bfloat162float(h23.x));
        h23.y = __float2bfloat16(v.w); l23.y = __float2bfloat16(v.w - __bfloat162float(h23.y));
        *(__nv_bfloat162*)&smb[AH_OFF + rr * A_STRIDE + kcol] = h01;
        *(__nv_bfloat162*)&smb[AH_OFF + rr * A_STRIDE + kcol + 2] = h23;
        *(__nv_bfloat162*)&smb[AL_OFF + rr * A_STRIDE + kcol] = l01;
        *(__nv_bfloat162*)&smb[AL_OFF + rr * A_STRIDE + kcol + 2] = l23;
    }
    // ---- phase 1b: CSR aggregate + mean -> cols 0..127 ----
    for (int j = 0; j < 8; j++) {
        int rr = w * 8 + j, row = m0 + rr;
        float4 acc = make_float4(0.f, 0.f, 0.f, 0.f);
        if (row < NN) {
            int beg = __ldg(rowptr + row), end = __ldg(rowptr + row + 1);
            int e = beg;
            for (; e + 4 <= end; e += 4) {
                int s0 = __ldg(colidx + e), s1 = __ldg(colidx + e + 1);
                int s2 = __ldg(colidx + e + 2), s3 = __ldg(colidx + e + 3);
                float4 v0 = xb4[(size_t)s0 * 32 + lane];
                float4 v1 = xb4[(size_t)s1 * 32 + lane];
                float4 v2 = xb4[(size_t)s2 * 32 + lane];
                float4 v3 = xb4[(size_t)s3 * 32 + lane];
                acc.x += v0.x + v1.x + v2.x + v3.x;
                acc.y += v0.y + v1.y + v2.y + v3.y;
                acc.z += v0.z + v1.z + v2.z + v3.z;
                acc.w += v0.w + v1.w + v2.w + v3.w;
            }
            for (; e < end; e++) {
                int s = __ldg(colidx + e);
                float4 v = xb4[(size_t)s * 32 + lane];
                acc.x += v.x; acc.y += v.y; acc.z += v.z; acc.w += v.w;
            }
            float inv = 1.f / fmaxf((float)(end - beg), 1.f);
            acc.x *= inv; acc.y *= inv; acc.z *= inv; acc.w *= inv;
        }
        int kcol = lane * 4;
        __nv_bfloat162 h01, h23, l01, l23;
        h01.x = __float2bfloat16(acc.x); l01.x = __float2bfloat16(acc.x - __bfloat162float(h01.x));
        h01.y = __float2bfloat16(acc.y); l01.y = __float2bfloat16(acc.y - __bfloat162float(h01.y));
        h23.x = __float2bfloat16(acc.z); l23.x = __float2bfloat16(acc.z - __bfloat162float(h23.x));
        h23.y = __float2bfloat16(acc.w); l23.y = __float2bfloat16(acc.w - __bfloat162float(h23.y));
        *(__nv_bfloat162*)&smb[AH_OFF + rr * A_STRIDE + kcol] = h01;
        *(__nv_bfloat162*)&smb[AH_OFF + rr * A_STRIDE + kcol + 2] = h23;
        *(__nv_bfloat162*)&smb[AL_OFF + rr * A_STRIDE + kcol] = l01;
        *(__nv_bfloat162*)&smb[AL_OFF + rr * A_STRIDE + kcol + 2] = l23;
    }

    // ---- stage W tile 0 (hi+lo), [128 n][16 k] padded to stride 24 ----
    int sn = tid >> 1, sh = tid & 1;  // n row, 8-elem half
    {
        float4 h = *(const float4*)(WHg + sn * 256 + sh * 8);
        float4 l = *(const float4*)(WLg + sn * 256 + sh * 8);
        *(float4*)&smb[WH_OFF + sn * 24 + sh * 8] = h;
        *(float4*)&smb[WL_OFF + sn * 24 + sh * 8] = l;
    }
    __syncthreads();

    // ---- main loop: 16 k-steps, double-buffered W ----
    int mtile = w & 3, nh = w >> 2;
    int g = lane >> 2, tg = lane & 3;
    int ar0 = (mtile * 16 + g) * A_STRIDE;
    int ar1 = ar0 + 8 * A_STRIDE;
    float acc[8][4];
#pragma unroll
    for (int j = 0; j < 8; j++)
#pragma unroll
        for (int q = 0; q < 4; q++) acc[j][q] = 0.f;

#pragma unroll 1
    for (int t = 0; t < 16; t++) {
        int k0 = t * 16;
        float4 ph, pl;
        if (t < 15) {
            ph = *(const float4*)(WHg + sn * 256 + k0 + 16 + sh * 8);
            pl = *(const float4*)(WLg + sn * 256 + k0 + 16 + sh * 8);
        }
        const __nv_bfloat16* WHb = smb + WH_OFF + (t & 1) * (128 * 24);
        const __nv_bfloat16* WLb = smb + WL_OFF + (t & 1) * (128 * 24);
        unsigned ah[4], al[4];
        ah[0] = *(const unsigned*)&smb[AH_OFF + ar0 + k0 + tg * 2];
        ah[1] = *(const unsigned*)&smb[AH_OFF + ar1 + k0 + tg * 2];
        ah[2] = *(const unsigned*)&smb[AH_OFF + ar0 + k0 + 8 + tg * 2];
        ah[3] = *(const unsigned*)&smb[AH_OFF + ar1 + k0 + 8 + tg * 2];
        al[0] = *(const unsigned*)&smb[AL_OFF + ar0 + k0 + tg * 2];
        al[1] = *(const unsigned*)&smb[AL_OFF + ar1 + k0 + tg * 2];
        al[2] = *(const unsigned*)&smb[AL_OFF + ar0 + k0 + 8 + tg * 2];
        al[3] = *(const unsigned*)&smb[AL_OFF + ar1 + k0 + 8 + tg * 2];
#pragma unroll
        for (int j = 0; j < 8; j++) {
            int n = nh * 64 + j * 8 + g;
            unsigned bh0 = *(const unsigned*)&WHb[n * 24 + tg * 2];
            unsigned bh1 = *(const unsigned*)&WHb[n * 24 + 8 + tg * 2];
            unsigned bl0 = *(const unsigned*)&WLb[n * 24 + tg * 2];
            unsigned bl1 = *(const unsigned*)&WLb[n * 24 + 8 + tg * 2];
            MMA_BF16(acc[j], ah, bh0, bh1);
            MMA_BF16(acc[j], ah, bl0, bl1);
            MMA_BF16(acc[j], al, bh0, bh1);
        }
        if (t < 15) {
            int nb = (t + 1) & 1;
            *(float4*)&smb[WH_OFF + nb * (128 * 24) + sn * 24 + sh * 8] = ph;
            *(float4*)&smb[WL_OFF + nb * (128 * 24) + sn * 24 + sh * 8] = pl;
            __syncthreads();
        }
    }

    // ---- epilogue: bias + relu, float2 stores ----
    int r0 = m0 + mtile * 16 + g;
    int r1 = r0 + 8;
#pragma unroll
    for (int j = 0; j < 8; j++) {
        int n0 = nh * 64 + j * 8 + tg * 2;
        float b0 = __ldg(bias + n0), b1 = __ldg(bias + n0 + 1);
        if (r0 < NN) {
            float2 o;
            o.x = fmaxf(acc[j][0] + b0, 0.f);
            o.y = fmaxf(acc[j][1] + b1, 0.f);
            *(float2*)&O[(size_t)r0 * HH + n0] = o;
        }
        if (r1 < NN) {
            float2 o;
            o.x = fmaxf(acc[j][2] + b0, 0.f);
            o.y = fmaxf(acc[j][3] + b1, 0.f);
            *(float2*)&O[(size_t)r1 * HH + n0] = o;
        }
    }
}

// ---------------- host ----------------
extern "C" void kernel_launch(void* const* d_in, const int* in_sizes, int n_in,
                              void* d_out, int out_size) {
    const float* x = (const float*)d_in[0];
    const int* ei = (const int*)d_in[1];
    const float* Wl = (const float*)d_in[2];
    const float* bl = (const float*)d_in[3];
    const float* Wr = (const float*)d_in[4];
    float* out = (float*)d_out;
    (void)in_sizes; (void)n_in; (void)out_size;

    // ---- derive all JAX subkeys on host (partitionable semantics) ----
    unsigned kp[RR][2], kn[RR][2], s1k[RR][2], s2k[RR][2];
    for (int r = 0; r < RR; r++) {
        unsigned f0, f1;
        tf2x32(0u, 42u, 0u, (unsigned)r, f0, f1);           // fold_in
        tf2x32(f0, f1, 0u, 0u, kp[r][0], kp[r][1]);         // split[0]
        tf2x32(f0, f1, 0u, 1u, kn[r][0], kn[r][1]);         // split[1]
        unsigned pk0, pk1;
        tf2x32(f0, f1, 0u, 2u, pk0, pk1);                   // split[2] = kperm
        unsigned key10, key11;
        tf2x32(pk0, pk1, 0u, 0u, key10, key11);             // round1 new key
        tf2x32(pk0, pk1, 0u, 1u, s1k[r][0], s1k[r][1]);     // round1 use key
        tf2x32(key10, key11, 0u, 1u, s2k[r][0], s2k[r][1]); // round2 use key
    }

    // set attributes unconditionally every call (no static guards)
    cudaFuncSetAttribute(agg_gemm_kernel, cudaFuncAttributeMaxDynamicSharedMemorySize,
                         SMEM_ELEMS * 2);

    void *p_xpos = nullptr, *p_xneg = nullptr, *p_inv = nullptr;
    void *p_rowptr = nullptr, *p_col = nullptr, *p_whi = nullptr, *p_wlo = nullptr;
    cudaGetSymbolAddress(&p_xpos, g_xpos);
    cudaGetSymbolAddress(&p_xneg, g_xneg);
    cudaGetSymbolAddress(&p_inv, g_inv);
    cudaGetSymbolAddress(&p_rowptr, g_rowptr);
    cudaGetSymbolAddress(&p_col, g_col);
    cudaGetSymbolAddress(&p_whi, g_Wthi);
    cudaGetSymbolAddress(&p_wlo, g_Wtlo);
    float* xpos = (float*)p_xpos;
    float* xneg = (float*)p_xneg;
    int* invp = (int*)p_inv;
    int* rowptr = (int*)p_rowptr;
    int* colidx = (int*)p_col;
    __nv_bfloat16* whi = (__nv_bfloat16*)p_whi;
    __nv_bfloat16* wlo = (__nv_bfloat16*)p_wlo;

    // ---- W pre-convert (once per launch) ----
    wconv_kernel<<<(RR * 128 * 256 + 255) / 256, 256>>>(Wl, Wr);

    // ---- CSR build (once per launch) ----
    const int NB = (NN + 1023) / 1024;  // 49
    csr_zero<<<(RR * NN + 255) / 256, 256>>>();
    csr_hist<<<(RR * EE + 255) / 256, 256>>>(ei);
    scan1<<<dim3(NB, RR), 1024>>>();
    scan2<<<RR, 32>>>(NB);
    scan3<<<dim3(NB, RR), 1024>>>();
    csr_fill<<<(RR * EE + 255) / 256, 256>>>(ei);

    // ---- permutations: MSD buckets + counting rank (both rounds concurrent) ----
    Keys12 KK;
    for (int r = 0; r < RR; r++) {
        KK.k[0 + 2 * r] = s1k[r][0]; KK.k[0 + 2 * r + 1] = s1k[r][1];
        KK.k[6 + 2 * r] = s2k[r][0]; KK.k[6 + 2 * r + 1] = s2k[r][1];
    }
    dim3 eg((NN + 255) / 256, RR, 2);
    bzero_kernel<<<(2 * RR * NBKT + 255) / 256, 256>>>();
    keyhist_kernel<<<eg, 256>>>(KK);
    bprefix_kernel<<<dim3(RR, 2), NBKT>>>();
    bscatter_kernel<<<eg, 256>>>();
    brank_kernel<<<(2 * RR * NBKT * 32 + 255) / 256, 256>>>();
    dim3 cg((NN + 255) / 256, RR);
    compose_invperm_kernel<<<cg, 256>>>();

    // ---- per-relation pipeline ----
    const int dropBlocks = (NN * 32 + 255) / 256;
    const int gemmBlocks = (NN + 63) / 64;
    for (int r = 0; r < RR; r++) {
        const float* bb = bl + (size_t)r * HH;
        const __nv_bfloat16* WH = whi + (size_t)r * 128 * 256;
        const __nv_bfloat16* WL = wlo + (size_t)r * 128 * 256;
        dropboth_kernel<<<dropBlocks, 256>>>(x, invp + (size_t)r * NN,
                                             kp[r][0], kp[r][1], kn[r][0], kn[r][1]);
        agg_gemm_kernel<<<gemmBlocks, 256, SMEM_ELEMS * 2>>>(
            xpos, rowptr + (size_t)r * (NN + 1), colidx + (size_t)r * EE,
            WH, WL, bb, out + (size_t)r * NN * HH);
        agg_gemm_kernel<<<gemmBlocks, 256, SMEM_ELEMS * 2>>>(
            xneg, rowptr + (size_t)r * (NN + 1), colidx + (size_t)r * EE,
            WH, WL, bb, out + (size_t)(RR + r) * NN * HH);
    }
}

// round 12
// speedup vs baseline: 1.5559x; 1.2699x over previous
#include <cuda_runtime.h>
#include <cuda_bf16.h>
#include <cstdint>

#define NN 50000
#define EE 500000
#define DD 128
#define HH 128
#define RR 3
#define NBKT 1024   // MSD buckets (top 10 bits)

// ---------------- device scratch (static, no runtime alloc) ----------------
// 6 dropped buffers: p = 2*r + (0 pos | 1 neg)
__device__ float g_xbuf[2 * RR][NN * DD];
__device__ int g_inv[RR][NN];                       // inverse of final permutation
// MSD bucket machinery, per round x relation
__device__ unsigned g_key[2][RR][NN];
__device__ unsigned long long g_pairs[2][RR][NN];   // (key<<32)|idx
__device__ int g_arg[2][RR][NN];                    // argsort result per round
__device__ int g_bhist[2][RR][NBKT];
__device__ int g_bfill[2][RR][NBKT];
__device__ int g_bstart[2][RR][NBKT + 1];
// CSR
__device__ int g_deg[RR][NN];
__device__ int g_fill[RR][NN];
__device__ int g_rowptr[RR][NN + 1];
__device__ int g_col[RR][EE];
__device__ unsigned g_bs[RR][64];
__device__ unsigned g_bo[RR][64];
// pre-converted W: transposed [n][k], k=0..255 = [W1;W2], split hi/lo bf16
__device__ __nv_bfloat16 g_Wthi[RR][128 * 256];
__device__ __nv_bfloat16 g_Wtlo[RR][128 * 256];

// ---------------- JAX threefry2x32 (exact, 20 rounds) ----------------
__host__ __device__ __forceinline__ void tf2x32(unsigned k0, unsigned k1,
                                                unsigned x0, unsigned x1,
                                                unsigned& o0, unsigned& o1) {
    unsigned ks0 = k0, ks1 = k1, ks2 = k0 ^ k1 ^ 0x1BD11BDAu;
    x0 += ks0; x1 += ks1;
#define TFR(r) { x0 += x1; x1 = (x1 << (r)) | (x1 >> (32 - (r))); x1 ^= x0; }
    TFR(13) TFR(15) TFR(26) TFR(6)   x0 += ks1; x1 += ks2 + 1u;
    TFR(17) TFR(29) TFR(16) TFR(24)  x0 += ks2; x1 += ks0 + 2u;
    TFR(13) TFR(15) TFR(26) TFR(6)   x0 += ks0; x1 += ks1 + 3u;
    TFR(17) TFR(29) TFR(16) TFR(24)  x0 += ks1; x1 += ks2 + 4u;
    TFR(13) TFR(15) TFR(26) TFR(6)   x0 += ks2; x1 += ks0 + 5u;
#undef TFR
    o0 = x0; o1 = x1;
}

__device__ __forceinline__ unsigned pbits(unsigned k0, unsigned k1, unsigned i) {
    unsigned o0, o1;
    tf2x32(k0, k1, 0u, i, o0, o1);
    return o0 ^ o1;
}

struct Keys12 { unsigned k[12]; };  // [round*6 + r*2 + {0,1}] (shuffle keys)

// ================= permutation machinery: MSD buckets + counting rank ==========
__global__ void bzero_kernel() {
    int i = blockIdx.x * blockDim.x + threadIdx.x;
    if (i < 2 * RR * NBKT) {
        ((int*)g_bhist)[i] = 0;
        ((int*)g_bfill)[i] = 0;
    }
}

__global__ void keyhist_kernel(Keys12 ks) {
    int r = blockIdx.y, round = blockIdx.z;
    int i = blockIdx.x * blockDim.x + threadIdx.x;
    if (i >= NN) return;
    unsigned k0 = ks.k[round * 6 + 2 * r], k1 = ks.k[round * 6 + 2 * r + 1];
    unsigned key = pbits(k0, k1, (unsigned)i);
    g_key[round][r][i] = key;
    atomicAdd(&g_bhist[round][r][key >> 22], 1);
}

__global__ void bprefix_kernel() {
    __shared__ unsigned s[NBKT];
    int r = blockIdx.x, round = blockIdx.y, tid = threadIdx.x;
    unsigned v = (unsigned)g_bhist[round][r][tid];
    s[tid] = v;
    __syncthreads();
    unsigned incl = v;
    for (int o = 1; o < NBKT; o <<= 1) {
        unsigned add = (tid >= o) ? s[tid - o] : 0u;
        __syncthreads();
        incl += add; s[tid] = incl;
        __syncthreads();
    }
    g_bstart[round][r][tid + 1] = (int)incl;
    if (tid == 0) g_bstart[round][r][0] = 0;
}

__global__ void bscatter_kernel() {
    int r = blockIdx.y, round = blockIdx.z;
    int i = blockIdx.x * blockDim.x + threadIdx.x;
    if (i >= NN) return;
    unsigned key = g_key[round][r][i];
    int b = (int)(key >> 22);
    int pos = g_bstart[round][r][b] + atomicAdd(&g_bfill[round][r][b], 1);
    g_pairs[round][r][pos] = ((unsigned long long)key << 32) | (unsigned)i;
}

__global__ void brank_kernel() {
    int gwarp = (blockIdx.x * blockDim.x + threadIdx.x) >> 5;
    int lane = threadIdx.x & 31;
    if (gwarp >= 2 * RR * NBKT) return;
    int round = gwarp / (RR * NBKT);
    int rem = gwarp - round * RR * NBKT;
    int r = rem >> 10, b = rem & (NBKT - 1);
    int base = g_bstart[round][r][b];
    int end = g_bstart[round][r][b + 1];
    int m = end - base;
    const unsigned long long* P = g_pairs[round][r];
    int* A = g_arg[round][r];
    for (int e = lane; e < m; e += 32) {
        unsigned long long me = P[base + e];
        int cnt = 0;
        for (int j = 0; j < m; j++) cnt += (P[base + j] < me) ? 1 : 0;
        A[base + cnt] = (int)(me & 0xffffffffu);
    }
}

__global__ void compose_invperm_kernel() {
    int r = blockIdx.y;
    int j = blockIdx.x * blockDim.x + threadIdx.x;
    if (j >= NN) return;
    int a2 = g_arg[1][r][j];
    int p = g_arg[0][r][a2];
    g_inv[r][p] = j;
}

// ================= CSR build =================
__global__ void csr_zero() {
    int i = blockIdx.x * blockDim.x + threadIdx.x;
    if (i < RR * NN) { ((int*)g_deg)[i] = 0; ((int*)g_fill)[i] = 0; }
}
__global__ void csr_hist(const int* __restrict__ ei) {
    int idx = blockIdx.x * blockDim.x + threadIdx.x;
    if (idx >= RR * EE) return;
    int r = idx / EE, e = idx - r * EE;
    int t = __ldg(ei + (size_t)r * 2 * EE + EE + e);
    atomicAdd(&g_deg[r][t], 1);
}
__global__ void scan1() {
    __shared__ unsigned s[1024];
    int r = blockIdx.y, b = blockIdx.x, tid = threadIdx.x;
    int i = b * 1024 + tid;
    unsigned v = (i < NN) ? (unsigned)g_deg[r][i] : 0u;
    s[tid] = v;
    __syncthreads();
    unsigned incl = v;
    for (int o = 1; o < 1024; o <<= 1) {
        unsigned add = (tid >= o) ? s[tid - o] : 0u;
        __syncthreads();
        incl += add; s[tid] = incl;
        __syncthreads();
    }
    if (i < NN) g_rowptr[r][i + 1] = (int)incl;
    if (tid == 1023) g_bs[r][b] = incl;
}
__global__ void scan2(int nb) {
    int r = blockIdx.x;
    if (threadIdx.x == 0) {
        unsigned run = 0;
        for (int b = 0; b < nb; b++) { unsigned t = g_bs[r][b]; g_bo[r][b] = run; run += t; }
    }
}
__global__ void scan3() {
    int r = blockIdx.y, b = blockIdx.x;
    int i = b * 1024 + threadIdx.x;
    if (i < NN) g_rowptr[r][i + 1] += (int)g_bo[r][b];
    if (b == 0 && threadIdx.x == 0) g_rowptr[r][0] = 0;
}
__global__ void csr_fill(const int* __restrict__ ei) {
    int idx = blockIdx.x * blockDim.x + threadIdx.x;
    if (idx >= RR * EE) return;
    int r = idx / EE, e = idx - r * EE;
    int s = __ldg(ei + (size_t)r * 2 * EE + e);
    int t = __ldg(ei + (size_t)r * 2 * EE + EE + e);
    int p = g_rowptr[r][t] + atomicAdd(&g_fill[r][t], 1);
    g_col[r][p] = s;
}

// ================= W pre-convert: transpose + bf16 hi/lo split =================
__global__ void wconv_kernel(const float* __restrict__ Wl, const float* __restrict__ Wr) {
    int idx = blockIdx.x * blockDim.x + threadIdx.x;
    if (idx >= RR * 128 * 256) return;
    int r = idx / (128 * 256);
    int rem = idx - r * 128 * 256;
    int n = rem >> 8, k = rem & 255;
    float v = (k < DD) ? Wl[(size_t)r * DD * HH + (size_t)k * HH + n]
                       : Wr[(size_t)r * DD * HH + (size_t)(k - DD) * HH + n];
    __nv_bfloat16 hi = __float2bfloat16(v);
    __nv_bfloat16 lo = __float2bfloat16(v - __bfloat162float(hi));
    g_Wthi[r][n * 256 + k] = hi;
    g_Wtlo[r][n * 256 + k] = lo;
}

// ======= fused pos+neg dropout for ALL relations (+ permutation scatter) =======
struct DropKeys { unsigned k[12]; };  // [r*4 + {kp0,kp1,kn0,kn1}]
__global__ void dropall_kernel(const float* __restrict__ x, DropKeys dk) {
    int r = blockIdx.z;
    int i4 = blockIdx.x * blockDim.x + threadIdx.x;
    if (i4 >= NN * 32) return;
    unsigned kp0 = dk.k[r * 4 + 0], kp1 = dk.k[r * 4 + 1];
    unsigned kn0 = dk.k[r * 4 + 2], kn1 = dk.k[r * 4 + 3];
    int row = i4 >> 5, c = i4 & 31;
    float4 v = ((const float4*)x)[i4];
    unsigned base = (unsigned)i4 * 4u;
    float4 p, n;
    p.x = (pbits(kp0, kp1, base + 0u) & 0x80000000u) ? 0.f : 2.f * v.x;
    p.y = (pbits(kp0, kp1, base + 1u) & 0x80000000u) ? 0.f : 2.f * v.y;
    p.z = (pbits(kp0, kp1, base + 2u) & 0x80000000u) ? 0.f : 2.f * v.z;
    p.w = (pbits(kp0, kp1, base + 3u) & 0x80000000u) ? 0.f : 2.f * v.w;
    n.x = (pbits(kn0, kn1, base + 0u) & 0x80000000u) ? 0.f : 2.f * v.x;
    n.y = (pbits(kn0, kn1, base + 1u) & 0x80000000u) ? 0.f : 2.f * v.y;
    n.z = (pbits(kn0, kn1, base + 2u) & 0x80000000u) ? 0.f : 2.f * v.z;
    n.w = (pbits(kn0, kn1, base + 3u) & 0x80000000u) ? 0.f : 2.f * v.w;
    ((float4*)g_xbuf[2 * r])[i4] = p;
    ((float4*)g_xbuf[2 * r + 1])[(size_t)g_inv[r][row] * 32 + c] = n;
}

// ======== fused CSR-aggregate + mean + split-bf16 tensor-core dual GEMM ========
// ONE launch for all 6 passes: blockIdx.y = p = 2*r + (0 pos | 1 neg).
// 64-row M tile, 512 threads (16 warps). K=256 = [agg(128) | x(128)].
// acc = Ahi@Whi + Ahi@Wlo + Alo@Whi  (fp32 accumulate)
#define A_STRIDE 264
#define AH_OFF 0
#define AL_OFF (64 * A_STRIDE)
#define WH_OFF (2 * 64 * A_STRIDE)
#define WL_OFF (WH_OFF + 2 * 128 * 24)
#define SMEM_ELEMS (WL_OFF + 2 * 128 * 24)   // 46080 bf16 = 92160 B

#define MMA_BF16(d, a, b0v, b1v) \
    asm volatile("mma.sync.aligned.m16n8k16.row.col.f32.bf16.bf16.f32 " \
        "{%0,%1,%2,%3}, {%4,%5,%6,%7}, {%8,%9}, {%0,%1,%2,%3};" \
        : "+f"(d[0]), "+f"(d[1]), "+f"(d[2]), "+f"(d[3]) \
        : "r"(a[0]), "r"(a[1]), "r"(a[2]), "r"(a[3]), "r"(b0v), "r"(b1v))

__global__ void __launch_bounds__(512, 2) agg_gemm_kernel(
        const float* __restrict__ bl, float* __restrict__ O) {
    extern __shared__ __nv_bfloat16 smb[];
    int tid = threadIdx.x, lane = tid & 31, w = tid >> 5;
    int p = blockIdx.y, r = p >> 1, sneg = p & 1;
    int m0 = blockIdx.x * 64;
    const float4* xb4 = (const float4*)g_xbuf[p];
    const int* rowptr = g_rowptr[r];
    const int* colidx = g_col[r];
    const __nv_bfloat16* WHg = g_Wthi[r];
    const __nv_bfloat16* WLg = g_Wtlo[r];
    const float* bias = bl + r * HH;
    float* out = O + (size_t)(sneg ? (RR + r) : r) * NN * HH;

    // ---- phase 1a: own x rows -> cols 128..255 (512 threads) ----
    for (int i = tid; i < 64 * 32; i += 512) {
        int rr = i >> 5, cc = i & 31, row = m0 + rr;
        float4 v = (row < NN) ? xb4[(size_t)row * 32 + cc] : make_float4(0.f, 0.f, 0.f, 0.f);
        int kcol = 128 + cc * 4;
        __nv_bfloat162 h01, h23, l01, l23;
        h01.x = __float2bfloat16(v.x); l01.x = __float2bfloat16(v.x - __bfloat162float(h01.x));
        h01.y = __float2bfloat16(v.y); l01.y = __float2bfloat16(v.y - __bfloat162float(h01.y));
        h23.x = __float2bfloat16(v.z); l23.x = __float2bfloat16(v.z - __bfloat162float(h23.x));
        h23.y = __float2bfloat16(v.w); l23.y = __float2bfloat16(v.w - __bfloat162float(h23.y));
        *(__nv_bfloat162*)&smb[AH_OFF + rr * A_STRIDE + kcol] = h01;
        *(__nv_bfloat162*)&smb[AH_OFF + rr * A_STRIDE + kcol + 2] = h23;
        *(__nv_bfloat162*)&smb[AL_OFF + rr * A_STRIDE + kcol] = l01;
        *(__nv_bfloat162*)&smb[AL_OFF + rr * A_STRIDE + kcol + 2] = l23;
    }
    // ---- phase 1b: CSR aggregate + mean -> cols 0..127 (16 warps x 4 rows) ----
    for (int j = 0; j < 4; j++) {
        int rr = w * 4 + j, row = m0 + rr;
        float4 acc = make_float4(0.f, 0.f, 0.f, 0.f);
        if (row < NN) {
            int beg = __ldg(rowptr + row), end = __ldg(rowptr + row + 1);
            int e = beg;
            for (; e + 4 <= end; e += 4) {
                int s0 = __ldg(colidx + e), s1 = __ldg(colidx + e + 1);
                int s2 = __ldg(colidx + e + 2), s3 = __ldg(colidx + e + 3);
                float4 v0 = xb4[(size_t)s0 * 32 + lane];
                float4 v1 = xb4[(size_t)s1 * 32 + lane];
                float4 v2 = xb4[(size_t)s2 * 32 + lane];
                float4 v3 = xb4[(size_t)s3 * 32 + lane];
                acc.x += v0.x + v1.x + v2.x + v3.x;
                acc.y += v0.y + v1.y + v2.y + v3.y;
                acc.z += v0.z + v1.z + v2.z + v3.z;
                acc.w += v0.w + v1.w + v2.w + v3.w;
            }
            for (; e < end; e++) {
                int s = __ldg(colidx + e);
                float4 v = xb4[(size_t)s * 32 + lane];
                acc.x += v.x; acc.y += v.y; acc.z += v.z; acc.w += v.w;
            }
            float inv = 1.f / fmaxf((float)(end - beg), 1.f);
            acc.x *= inv; acc.y *= inv; acc.z *= inv; acc.w *= inv;
        }
        int kcol = lane * 4;
        __nv_bfloat162 h01, h23, l01, l23;
        h01.x = __float2bfloat16(acc.x); l01.x = __float2bfloat16(acc.x - __bfloat162float(h01.x));
        h01.y = __float2bfloat16(acc.y); l01.y = __float2bfloat16(acc.y - __bfloat162float(h01.y));
        h23.x = __float2bfloat16(acc.z); l23.x = __float2bfloat16(acc.z - __bfloat162float(h23.x));
        h23.y = __float2bfloat16(acc.w); l23.y = __float2bfloat16(acc.w - __bfloat162float(h23.y));
        *(__nv_bfloat162*)&smb[AH_OFF + rr * A_STRIDE + kcol] = h01;
        *(__nv_bfloat162*)&smb[AH_OFF + rr * A_STRIDE + kcol + 2] = h23;
        *(__nv_bfloat162*)&smb[AL_OFF + rr * A_STRIDE + kcol] = l01;
        *(__nv_bfloat162*)&smb[AL_OFF + rr * A_STRIDE + kcol + 2] = l23;
    }

    // ---- stage W tile 0 (hi+lo): threads 0..255 ----
    int sn = tid >> 1, sh = tid & 1;
    if (tid < 256) {
        float4 h = *(const float4*)(WHg + sn * 256 + sh * 8);
        float4 l = *(const float4*)(WLg + sn * 256 + sh * 8);
        *(float4*)&smb[WH_OFF + sn * 24 + sh * 8] = h;
        *(float4*)&smb[WL_OFF + sn * 24 + sh * 8] = l;
    }
    __syncthreads();

    // ---- main loop: 16 k-steps, double-buffered W ----
    int mtile = w & 3, nq = w >> 2;   // warp = (m16 tile, n32 quad)
    int g = lane >> 2, tg = lane & 3;
    int ar0 = (mtile * 16 + g) * A_STRIDE;
    int ar1 = ar0 + 8 * A_STRIDE;
    float acc[4][4];
#pragma unroll
    for (int j = 0; j < 4; j++)
#pragma unroll
        for (int q = 0; q < 4; q++) acc[j][q] = 0.f;

#pragma unroll 1
    for (int t = 0; t < 16; t++) {
        int k0 = t * 16;
        float4 ph, pl;
        if (t < 15 && tid < 256) {
            ph = *(const float4*)(WHg + sn * 256 + k0 + 16 + sh * 8);
            pl = *(const float4*)(WLg + sn * 256 + k0 + 16 + sh * 8);
        }
        const __nv_bfloat16* WHb = smb + WH_OFF + (t & 1) * (128 * 24);
        const __nv_bfloat16* WLb = smb + WL_OFF + (t & 1) * (128 * 24);
        unsigned ah[4], al[4];
        ah[0] = *(const unsigned*)&smb[AH_OFF + ar0 + k0 + tg * 2];
        ah[1] = *(const unsigned*)&smb[AH_OFF + ar1 + k0 + tg * 2];
        ah[2] = *(const unsigned*)&smb[AH_OFF + ar0 + k0 + 8 + tg * 2];
        ah[3] = *(const unsigned*)&smb[AH_OFF + ar1 + k0 + 8 + tg * 2];
        al[0] = *(const unsigned*)&smb[AL_OFF + ar0 + k0 + tg * 2];
        al[1] = *(const unsigned*)&smb[AL_OFF + ar1 + k0 + tg * 2];
        al[2] = *(const unsigned*)&smb[AL_OFF + ar0 + k0 + 8 + tg * 2];
        al[3] = *(const unsigned*)&smb[AL_OFF + ar1 + k0 + 8 + tg * 2];
#pragma unroll
        for (int j = 0; j < 4; j++) {
            int n = nq * 32 + j * 8 + g;
            unsigned bh0 = *(const unsigned*)&WHb[n * 24 + tg * 2];
            unsigned bh1 = *(const unsigned*)&WHb[n * 24 + 8 + tg * 2];
            unsigned bl0 = *(const unsigned*)&WLb[n * 24 + tg * 2];
            unsigned bl1 = *(const unsigned*)&WLb[n * 24 + 8 + tg * 2];
            MMA_BF16(acc[j], ah, bh0, bh1);
            MMA_BF16(acc[j], ah, bl0, bl1);
            MMA_BF16(acc[j], al, bh0, bh1);
        }
        if (t < 15) {
            int nb = (t + 1) & 1;
            if (tid < 256) {
                *(float4*)&smb[WH_OFF + nb * (128 * 24) + sn * 24 + sh * 8] = ph;
                *(float4*)&smb[WL_OFF + nb * (128 * 24) + sn * 24 + sh * 8] = pl;
            }
            __syncthreads();
        }
    }

    // ---- epilogue: bias + relu, float2 stores ----
    int r0 = m0 + mtile * 16 + g;
    int r1 = r0 + 8;
#pragma unroll
    for (int j = 0; j < 4; j++) {
        int n0 = nq * 32 + j * 8 + tg * 2;
        float b0 = __ldg(bias + n0), b1 = __ldg(bias + n0 + 1);
        if (r0 < NN) {
            float2 o;
            o.x = fmaxf(acc[j][0] + b0, 0.f);
            o.y = fmaxf(acc[j][1] + b1, 0.f);
            *(float2*)&out[(size_t)r0 * HH + n0] = o;
        }
        if (r1 < NN) {
            float2 o;
            o.x = fmaxf(acc[j][2] + b0, 0.f);
            o.y = fmaxf(acc[j][3] + b1, 0.f);
            *(float2*)&out[(size_t)r1 * HH + n0] = o;
        }
    }
}

// ---------------- host ----------------
extern "C" void kernel_launch(void* const* d_in, const int* in_sizes, int n_in,
                              void* d_out, int out_size) {
    const float* x = (const float*)d_in[0];
    const int* ei = (const int*)d_in[1];
    const float* Wl = (const float*)d_in[2];
    const float* bl = (const float*)d_in[3];
    const float* Wr = (const float*)d_in[4];
    float* out = (float*)d_out;
    (void)in_sizes; (void)n_in; (void)out_size;

    // ---- derive all JAX subkeys on host (partitionable semantics) ----
    unsigned kp[RR][2], kn[RR][2], s1k[RR][2], s2k[RR][2];
    for (int r = 0; r < RR; r++) {
        unsigned f0, f1;
        tf2x32(0u, 42u, 0u, (unsigned)r, f0, f1);           // fold_in
        tf2x32(f0, f1, 0u, 0u, kp[r][0], kp[r][1]);         // split[0]
        tf2x32(f0, f1, 0u, 1u, kn[r][0], kn[r][1]);         // split[1]
        unsigned pk0, pk1;
        tf2x32(f0, f1, 0u, 2u, pk0, pk1);                   // split[2] = kperm
        unsigned key10, key11;
        tf2x32(pk0, pk1, 0u, 0u, key10, key11);             // round1 new key
        tf2x32(pk0, pk1, 0u, 1u, s1k[r][0], s1k[r][1]);     // round1 use key
        tf2x32(key10, key11, 0u, 1u, s2k[r][0], s2k[r][1]); // round2 use key
    }

    cudaFuncSetAttribute(agg_gemm_kernel, cudaFuncAttributeMaxDynamicSharedMemorySize,
                         SMEM_ELEMS * 2);

    // ---- W pre-convert (once per launch) ----
    wconv_kernel<<<(RR * 128 * 256 + 255) / 256, 256>>>(Wl, Wr);

    // ---- CSR build (once per launch) ----
    const int NB = (NN + 1023) / 1024;  // 49
    csr_zero<<<(RR * NN + 255) / 256, 256>>>();
    csr_hist<<<(RR * EE + 255) / 256, 256>>>(ei);
    scan1<<<dim3(NB, RR), 1024>>>();
    scan2<<<RR, 32>>>(NB);
    scan3<<<dim3(NB, RR), 1024>>>();
    csr_fill<<<(RR * EE + 255) / 256, 256>>>(ei);

    // ---- permutations: MSD buckets + counting rank (both rounds concurrent) ----
    Keys12 KK;
    for (int r = 0; r < RR; r++) {
        KK.k[0 + 2 * r] = s1k[r][0]; KK.k[0 + 2 * r + 1] = s1k[r][1];
        KK.k[6 + 2 * r] = s2k[r][0]; KK.k[6 + 2 * r + 1] = s2k[r][1];
    }
    dim3 eg((NN + 255) / 256, RR, 2);
    bzero_kernel<<<(2 * RR * NBKT + 255) / 256, 256>>>();
    keyhist_kernel<<<eg, 256>>>(KK);
    bprefix_kernel<<<dim3(RR, 2), NBKT>>>();
    bscatter_kernel<<<eg, 256>>>();
    brank_kernel<<<(2 * RR * NBKT * 32 + 255) / 256, 256>>>();
    dim3 cg((NN + 255) / 256, RR);
    compose_invperm_kernel<<<cg, 256>>>();

    // ---- dropout: all relations, pos+neg, one launch ----
    DropKeys DK;
    for (int r = 0; r < RR; r++) {
        DK.k[r * 4 + 0] = kp[r][0]; DK.k[r * 4 + 1] = kp[r][1];
        DK.k[r * 4 + 2] = kn[r][0]; DK.k[r * 4 + 3] = kn[r][1];
    }
    dim3 dg((NN * 32 + 255) / 256, 1, RR);
    dropall_kernel<<<dg, 256>>>(x, DK);

    // ---- all 6 fused agg+GEMM passes in ONE launch ----
    const int gemmBlocks = (NN + 63) / 64;   // 782
    agg_gemm_kernel<<<dim3(gemmBlocks, 2 * RR), 512, SMEM_ELEMS * 2>>>(bl, out);
}

// round 13
// speedup vs baseline: 1.6216x; 1.0422x over previous
#include <cuda_runtime.h>
#include <cuda_bf16.h>
#include <cstdint>

#define NN 50000
#define EE 500000
#define DD 128
#define HH 128
#define RR 3
#define NBKT 1024   // MSD buckets (top 10 bits)

// ---------------- device scratch (static, no runtime alloc) ----------------
// 6 dropped buffers: p = 2*r + (0 pos | 1 neg)
__device__ float g_xbuf[2 * RR][NN * DD];
__device__ int g_inv[RR][NN];                       // inverse of final permutation
// MSD bucket machinery, per round x relation
__device__ unsigned g_key[2][RR][NN];
__device__ unsigned long long g_pairs[2][RR][NN];   // (key<<32)|idx
__device__ int g_arg[2][RR][NN];                    // argsort result per round
__device__ int g_bhist[2][RR][NBKT];
__device__ int g_bfill[2][RR][NBKT];
__device__ int g_bstart[2][RR][NBKT + 1];
// CSR
__device__ int g_deg[RR][NN];
__device__ int g_fill[RR][NN];
__device__ int g_rowptr[RR][NN + 1];
__device__ int g_col[RR][EE];
__device__ unsigned g_bs[RR][64];
__device__ unsigned g_bo[RR][64];
// pre-converted W: transposed [n][k], k=0..255 = [W1;W2], split hi/lo bf16
__device__ __nv_bfloat16 g_Wthi[RR][128 * 256];
__device__ __nv_bfloat16 g_Wtlo[RR][128 * 256];

// ---------------- JAX threefry2x32 (exact, 20 rounds) ----------------
__host__ __device__ __forceinline__ void tf2x32(unsigned k0, unsigned k1,
                                                unsigned x0, unsigned x1,
                                                unsigned& o0, unsigned& o1) {
    unsigned ks0 = k0, ks1 = k1, ks2 = k0 ^ k1 ^ 0x1BD11BDAu;
    x0 += ks0; x1 += ks1;
#define TFR(r) { x0 += x1; x1 = (x1 << (r)) | (x1 >> (32 - (r))); x1 ^= x0; }
    TFR(13) TFR(15) TFR(26) TFR(6)   x0 += ks1; x1 += ks2 + 1u;
    TFR(17) TFR(29) TFR(16) TFR(24)  x0 += ks2; x1 += ks0 + 2u;
    TFR(13) TFR(15) TFR(26) TFR(6)   x0 += ks0; x1 += ks1 + 3u;
    TFR(17) TFR(29) TFR(16) TFR(24)  x0 += ks1; x1 += ks2 + 4u;
    TFR(13) TFR(15) TFR(26) TFR(6)   x0 += ks2; x1 += ks0 + 5u;
#undef TFR
    o0 = x0; o1 = x1;
}

__device__ __forceinline__ unsigned pbits(unsigned k0, unsigned k1, unsigned i) {
    unsigned o0, o1;
    tf2x32(k0, k1, 0u, i, o0, o1);
    return o0 ^ o1;
}

struct Keys12 { unsigned k[12]; };  // [round*6 + r*2 + {0,1}] (shuffle keys)

// ================= permutation machinery: MSD buckets + counting rank ==========
__global__ void bzero_kernel() {
    int i = blockIdx.x * blockDim.x + threadIdx.x;
    if (i < 2 * RR * NBKT) {
        ((int*)g_bhist)[i] = 0;
        ((int*)g_bfill)[i] = 0;
    }
}

__global__ void keyhist_kernel(Keys12 ks) {
    int r = blockIdx.y, round = blockIdx.z;
    int i = blockIdx.x * blockDim.x + threadIdx.x;
    if (i >= NN) return;
    unsigned k0 = ks.k[round * 6 + 2 * r], k1 = ks.k[round * 6 + 2 * r + 1];
    unsigned key = pbits(k0, k1, (unsigned)i);
    g_key[round][r][i] = key;
    atomicAdd(&g_bhist[round][r][key >> 22], 1);
}

__global__ void bprefix_kernel() {
    __shared__ unsigned s[NBKT];
    int r = blockIdx.x, round = blockIdx.y, tid = threadIdx.x;
    unsigned v = (unsigned)g_bhist[round][r][tid];
    s[tid] = v;
    __syncthreads();
    unsigned incl = v;
    for (int o = 1; o < NBKT; o <<= 1) {
        unsigned add = (tid >= o) ? s[tid - o] : 0u;
        __syncthreads();
        incl += add; s[tid] = incl;
        __syncthreads();
    }
    g_bstart[round][r][tid + 1] = (int)incl;
    if (tid == 0) g_bstart[round][r][0] = 0;
}

__global__ void bscatter_kernel() {
    int r = blockIdx.y, round = blockIdx.z;
    int i = blockIdx.x * blockDim.x + threadIdx.x;
    if (i >= NN) return;
    unsigned key = g_key[round][r][i];
    int b = (int)(key >> 22);
    int pos = g_bstart[round][r][b] + atomicAdd(&g_bfill[round][r][b], 1);
    g_pairs[round][r][pos] = ((unsigned long long)key << 32) | (unsigned)i;
}

__global__ void brank_kernel() {
    int gwarp = (blockIdx.x * blockDim.x + threadIdx.x) >> 5;
    int lane = threadIdx.x & 31;
    if (gwarp >= 2 * RR * NBKT) return;
    int round = gwarp / (RR * NBKT);
    int rem = gwarp - round * RR * NBKT;
    int r = rem >> 10, b = rem & (NBKT - 1);
    int base = g_bstart[round][r][b];
    int end = g_bstart[round][r][b + 1];
    int m = end - base;
    const unsigned long long* P = g_pairs[round][r];
    int* A = g_arg[round][r];
    for (int e = lane; e < m; e += 32) {
        unsigned long long me = P[base + e];
        int cnt = 0;
        for (int j = 0; j < m; j++) cnt += (P[base + j] < me) ? 1 : 0;
        A[base + cnt] = (int)(me & 0xffffffffu);
    }
}

__global__ void compose_invperm_kernel() {
    int r = blockIdx.y;
    int j = blockIdx.x * blockDim.x + threadIdx.x;
    if (j >= NN) return;
    int a2 = g_arg[1][r][j];
    int p = g_arg[0][r][a2];
    g_inv[r][p] = j;
}

// ================= CSR build =================
__global__ void csr_zero() {
    int i = blockIdx.x * blockDim.x + threadIdx.x;
    if (i < RR * NN) { ((int*)g_deg)[i] = 0; ((int*)g_fill)[i] = 0; }
}
__global__ void csr_hist(const int* __restrict__ ei) {
    int idx = blockIdx.x * blockDim.x + threadIdx.x;
    if (idx >= RR * EE) return;
    int r = idx / EE, e = idx - r * EE;
    int t = __ldg(ei + (size_t)r * 2 * EE + EE + e);
    atomicAdd(&g_deg[r][t], 1);
}
__global__ void scan1() {
    __shared__ unsigned s[1024];
    int r = blockIdx.y, b = blockIdx.x, tid = threadIdx.x;
    int i = b * 1024 + tid;
    unsigned v = (i < NN) ? (unsigned)g_deg[r][i] : 0u;
    s[tid] = v;
    __syncthreads();
    unsigned incl = v;
    for (int o = 1; o < 1024; o <<= 1) {
        unsigned add = (tid >= o) ? s[tid - o] : 0u;
        __syncthreads();
        incl += add; s[tid] = incl;
        __syncthreads();
    }
    if (i < NN) g_rowptr[r][i + 1] = (int)incl;
    if (tid == 1023) g_bs[r][b] = incl;
}
__global__ void scan2(int nb) {
    int r = blockIdx.x;
    if (threadIdx.x == 0) {
        unsigned run = 0;
        for (int b = 0; b < nb; b++) { unsigned t = g_bs[r][b]; g_bo[r][b] = run; run += t; }
    }
}
__global__ void scan3() {
    int r = blockIdx.y, b = blockIdx.x;
    int i = b * 1024 + threadIdx.x;
    if (i < NN) g_rowptr[r][i + 1] += (int)g_bo[r][b];
    if (b == 0 && threadIdx.x == 0) g_rowptr[r][0] = 0;
}
__global__ void csr_fill(const int* __restrict__ ei) {
    int idx = blockIdx.x * blockDim.x + threadIdx.x;
    if (idx >= RR * EE) return;
    int r = idx / EE, e = idx - r * EE;
    int s = __ldg(ei + (size_t)r * 2 * EE + e);
    int t = __ldg(ei + (size_t)r * 2 * EE + EE + e);
    int p = g_rowptr[r][t] + atomicAdd(&g_fill[r][t], 1);
    g_col[r][p] = s;
}

// ================= W pre-convert: transpose + bf16 hi/lo split =================
__global__ void wconv_kernel(const float* __restrict__ Wl, const float* __restrict__ Wr) {
    int idx = blockIdx.x * blockDim.x + threadIdx.x;
    if (idx >= RR * 128 * 256) return;
    int r = idx / (128 * 256);
    int rem = idx - r * 128 * 256;
    int n = rem >> 8, k = rem & 255;
    float v = (k < DD) ? Wl[(size_t)r * DD * HH + (size_t)k * HH + n]
                       : Wr[(size_t)r * DD * HH + (size_t)(k - DD) * HH + n];
    __nv_bfloat16 hi = __float2bfloat16(v);
    __nv_bfloat16 lo = __float2bfloat16(v - __bfloat162float(hi));
    g_Wthi[r][n * 256 + k] = hi;
    g_Wtlo[r][n * 256 + k] = lo;
}

// ======= fused pos+neg dropout for ALL relations (+ permutation scatter) =======
struct DropKeys { unsigned k[12]; };  // [r*4 + {kp0,kp1,kn0,kn1}]
__global__ void dropall_kernel(const float* __restrict__ x, DropKeys dk) {
    int r = blockIdx.z;
    int i4 = blockIdx.x * blockDim.x + threadIdx.x;
    if (i4 >= NN * 32) return;
    unsigned kp0 = dk.k[r * 4 + 0], kp1 = dk.k[r * 4 + 1];
    unsigned kn0 = dk.k[r * 4 + 2], kn1 = dk.k[r * 4 + 3];
    int row = i4 >> 5, c = i4 & 31;
    float4 v = ((const float4*)x)[i4];
    unsigned base = (unsigned)i4 * 4u;
    float4 p, n;
    p.x = (pbits(kp0, kp1, base + 0u) & 0x80000000u) ? 0.f : 2.f * v.x;
    p.y = (pbits(kp0, kp1, base + 1u) & 0x80000000u) ? 0.f : 2.f * v.y;
    p.z = (pbits(kp0, kp1, base + 2u) & 0x80000000u) ? 0.f : 2.f * v.z;
    p.w = (pbits(kp0, kp1, base + 3u) & 0x80000000u) ? 0.f : 2.f * v.w;
    n.x = (pbits(kn0, kn1, base + 0u) & 0x80000000u) ? 0.f : 2.f * v.x;
    n.y = (pbits(kn0, kn1, base + 1u) & 0x80000000u) ? 0.f : 2.f * v.y;
    n.z = (pbits(kn0, kn1, base + 2u) & 0x80000000u) ? 0.f : 2.f * v.z;
    n.w = (pbits(kn0, kn1, base + 3u) & 0x80000000u) ? 0.f : 2.f * v.w;
    ((float4*)g_xbuf[2 * r])[i4] = p;
    ((float4*)g_xbuf[2 * r + 1])[(size_t)g_inv[r][row] * 32 + c] = n;
}

// ======== fused CSR-aggregate + mean + split-bf16 tensor-core dual GEMM ========
// ONE launch for all 6 passes: blockIdx.y = p = 2*r + (0 pos | 1 neg).
// 64-row M tile, 512 threads (16 warps). K=256 = [agg(128) | x(128)].
// acc = Ahi@Whi + Ahi@Wlo + Alo@Whi  (fp32 accumulate)
#define A_STRIDE 264
#define AH_OFF 0
#define AL_OFF (64 * A_STRIDE)
#define WH_OFF (2 * 64 * A_STRIDE)
#define WL_OFF (WH_OFF + 2 * 128 * 24)
#define SMEM_ELEMS (WL_OFF + 2 * 128 * 24)   // 46080 bf16 = 92160 B

#define MMA_BF16(d, a, b0v, b1v) \
    asm volatile("mma.sync.aligned.m16n8k16.row.col.f32.bf16.bf16.f32 " \
        "{%0,%1,%2,%3}, {%4,%5,%6,%7}, {%8,%9}, {%0,%1,%2,%3};" \
        : "+f"(d[0]), "+f"(d[1]), "+f"(d[2]), "+f"(d[3]) \
        : "r"(a[0]), "r"(a[1]), "r"(a[2]), "r"(a[3]), "r"(b0v), "r"(b1v))

__global__ void __launch_bounds__(512, 2) agg_gemm_kernel(
        const float* __restrict__ bl, float* __restrict__ O) {
    extern __shared__ __nv_bfloat16 smb[];
    int tid = threadIdx.x, lane = tid & 31, w = tid >> 5;
    int p = blockIdx.y, r = p >> 1, sneg = p & 1;
    int m0 = blockIdx.x * 64;
    const float4* xb4 = (const float4*)g_xbuf[p];
    const int* rowptr = g_rowptr[r];
    const int* colidx = g_col[r];
    const __nv_bfloat16* WHg = g_Wthi[r];
    const __nv_bfloat16* WLg = g_Wtlo[r];
    const float* bias = bl + r * HH;
    float* out = O + (size_t)(sneg ? (RR + r) : r) * NN * HH;

    // ---- phase 1a: own x rows -> cols 128..255 (512 threads) ----
    for (int i = tid; i < 64 * 32; i += 512) {
        int rr = i >> 5, cc = i & 31, row = m0 + rr;
        float4 v = (row < NN) ? xb4[(size_t)row * 32 + cc] : make_float4(0.f, 0.f, 0.f, 0.f);
        int kcol = 128 + cc * 4;
        __nv_bfloat162 h01, h23, l01, l23;
        h01.x = __float2bfloat16(v.x); l01.x = __float2bfloat16(v.x - __bfloat162float(h01.x));
        h01.y = __float2bfloat16(v.y); l01.y = __float2bfloat16(v.y - __bfloat162float(h01.y));
        h23.x = __float2bfloat16(v.z); l23.x = __float2bfloat16(v.z - __bfloat162float(h23.x));
        h23.y = __float2bfloat16(v.w); l23.y = __float2bfloat16(v.w - __bfloat162float(h23.y));
        *(__nv_bfloat162*)&smb[AH_OFF + rr * A_STRIDE + kcol] = h01;
        *(__nv_bfloat162*)&smb[AH_OFF + rr * A_STRIDE + kcol + 2] = h23;
        *(__nv_bfloat162*)&smb[AL_OFF + rr * A_STRIDE + kcol] = l01;
        *(__nv_bfloat162*)&smb[AL_OFF + rr * A_STRIDE + kcol + 2] = l23;
    }
    // ---- phase 1b: CSR aggregate + mean -> cols 0..127 (16 warps x 4 rows, MLP 8) ----
    for (int j = 0; j < 4; j++) {
        int rr = w * 4 + j, row = m0 + rr;
        float4 acc = make_float4(0.f, 0.f, 0.f, 0.f);
        if (row < NN) {
            int beg = __ldg(rowptr + row), end = __ldg(rowptr + row + 1);
            int e = beg;
            for (; e + 8 <= end; e += 8) {
                int s0 = __ldg(colidx + e), s1 = __ldg(colidx + e + 1);
                int s2 = __ldg(colidx + e + 2), s3 = __ldg(colidx + e + 3);
                int s4 = __ldg(colidx + e + 4), s5 = __ldg(colidx + e + 5);
                int s6 = __ldg(colidx + e + 6), s7 = __ldg(colidx + e + 7);
                float4 v0 = xb4[(size_t)s0 * 32 + lane];
                float4 v1 = xb4[(size_t)s1 * 32 + lane];
                float4 v2 = xb4[(size_t)s2 * 32 + lane];
                float4 v3 = xb4[(size_t)s3 * 32 + lane];
                float4 v4 = xb4[(size_t)s4 * 32 + lane];
                float4 v5 = xb4[(size_t)s5 * 32 + lane];
                float4 v6 = xb4[(size_t)s6 * 32 + lane];
                float4 v7 = xb4[(size_t)s7 * 32 + lane];
                acc.x += (v0.x + v1.x + v2.x + v3.x) + (v4.x + v5.x + v6.x + v7.x);
                acc.y += (v0.y + v1.y + v2.y + v3.y) + (v4.y + v5.y + v6.y + v7.y);
                acc.z += (v0.z + v1.z + v2.z + v3.z) + (v4.z + v5.z + v6.z + v7.z);
                acc.w += (v0.w + v1.w + v2.w + v3.w) + (v4.w + v5.w + v6.w + v7.w);
            }
            for (; e + 4 <= end; e += 4) {
                int s0 = __ldg(colidx + e), s1 = __ldg(colidx + e + 1);
                int s2 = __ldg(colidx + e + 2), s3 = __ldg(colidx + e + 3);
                float4 v0 = xb4[(size_t)s0 * 32 + lane];
                float4 v1 = xb4[(size_t)s1 * 32 + lane];
                float4 v2 = xb4[(size_t)s2 * 32 + lane];
                float4 v3 = xb4[(size_t)s3 * 32 + lane];
                acc.x += v0.x + v1.x + v2.x + v3.x;
                acc.y += v0.y + v1.y + v2.y + v3.y;
                acc.z += v0.z + v1.z + v2.z + v3.z;
                acc.w += v0.w + v1.w + v2.w + v3.w;
            }
            for (; e < end; e++) {
                int s = __ldg(colidx + e);
                float4 v = xb4[(size_t)s * 32 + lane];
                acc.x += v.x; acc.y += v.y; acc.z += v.z; acc.w += v.w;
            }
            float inv = 1.f / fmaxf((float)(end - beg), 1.f);
            acc.x *= inv; acc.y *= inv; acc.z *= inv; acc.w *= inv;
        }
        int kcol = lane * 4;
        __nv_bfloat162 h01, h23, l01, l23;
        h01.x = __float2bfloat16(acc.x); l01.x = __float2bfloat16(acc.x - __bfloat162float(h01.x));
        h01.y = __float2bfloat16(acc.y); l01.y = __float2bfloat16(acc.y - __bfloat162float(h01.y));
        h23.x = __float2bfloat16(acc.z); l23.x = __float2bfloat16(acc.z - __bfloat162float(h23.x));
        h23.y = __float2bfloat16(acc.w); l23.y = __float2bfloat16(acc.w - __bfloat162float(h23.y));
        *(__nv_bfloat162*)&smb[AH_OFF + rr * A_STRIDE + kcol] = h01;
        *(__nv_bfloat162*)&smb[AH_OFF + rr * A_STRIDE + kcol + 2] = h23;
        *(__nv_bfloat162*)&smb[AL_OFF + rr * A_STRIDE + kcol] = l01;
        *(__nv_bfloat162*)&smb[AL_OFF + rr * A_STRIDE + kcol + 2] = l23;
    }

    // ---- stage W tile 0 (hi+lo): threads 0..255 ----
    int sn = tid >> 1, sh = tid & 1;
    if (tid < 256) {
        float4 h = *(const float4*)(WHg + sn * 256 + sh * 8);
        float4 l = *(const float4*)(WLg + sn * 256 + sh * 8);
        *(float4*)&smb[WH_OFF + sn * 24 + sh * 8] = h;
        *(float4*)&smb[WL_OFF + sn * 24 + sh * 8] = l;
    }
    __syncthreads();

    // ---- main loop: 16 k-steps, double-buffered W ----
    int mtile = w & 3, nq = w >> 2;   // warp = (m16 tile, n32 quad)
    int g = lane >> 2, tg = lane & 3;
    int ar0 = (mtile * 16 + g) * A_STRIDE;
    int ar1 = ar0 + 8 * A_STRIDE;
    float acc[4][4];
#pragma unroll
    for (int j = 0; j < 4; j++)
#pragma unroll
        for (int q = 0; q < 4; q++) acc[j][q] = 0.f;

#pragma unroll 1
    for (int t = 0; t < 16; t++) {
        int k0 = t * 16;
        float4 ph, pl;
        if (t < 15 && tid < 256) {
            ph = *(const float4*)(WHg + sn * 256 + k0 + 16 + sh * 8);
            pl = *(const float4*)(WLg + sn * 256 + k0 + 16 + sh * 8);
        }
        const __nv_bfloat16* WHb = smb + WH_OFF + (t & 1) * (128 * 24);
        const __nv_bfloat16* WLb = smb + WL_OFF + (t & 1) * (128 * 24);
        unsigned ah[4], al[4];
        ah[0] = *(const unsigned*)&smb[AH_OFF + ar0 + k0 + tg * 2];
        ah[1] = *(const unsigned*)&smb[AH_OFF + ar1 + k0 + tg * 2];
        ah[2] = *(const unsigned*)&smb[AH_OFF + ar0 + k0 + 8 + tg * 2];
        ah[3] = *(const unsigned*)&smb[AH_OFF + ar1 + k0 + 8 + tg * 2];
        al[0] = *(const unsigned*)&smb[AL_OFF + ar0 + k0 + tg * 2];
        al[1] = *(const unsigned*)&smb[AL_OFF + ar1 + k0 + tg * 2];
        al[2] = *(const unsigned*)&smb[AL_OFF + ar0 + k0 + 8 + tg * 2];
        al[3] = *(const unsigned*)&smb[AL_OFF + ar1 + k0 + 8 + tg * 2];
#pragma unroll
        for (int j = 0; j < 4; j++) {
            int n = nq * 32 + j * 8 + g;
            unsigned bh0 = *(const unsigned*)&WHb[n * 24 + tg * 2];
            unsigned bh1 = *(const unsigned*)&WHb[n * 24 + 8 + tg * 2];
            unsigned bl0 = *(const unsigned*)&WLb[n * 24 + tg * 2];
            unsigned bl1 = *(const unsigned*)&WLb[n * 24 + 8 + tg * 2];
            MMA_BF16(acc[j], ah, bh0, bh1);
            MMA_BF16(acc[j], ah, bl0, bl1);
            MMA_BF16(acc[j], al, bh0, bh1);
        }
        if (t < 15) {
            int nb = (t + 1) & 1;
            if (tid < 256) {
                *(float4*)&smb[WH_OFF + nb * (128 * 24) + sn * 24 + sh * 8] = ph;
                *(float4*)&smb[WL_OFF + nb * (128 * 24) + sn * 24 + sh * 8] = pl;
            }
            __syncthreads();
        }
    }

    // ---- epilogue: bias + relu, float2 stores ----
    int r0 = m0 + mtile * 16 + g;
    int r1 = r0 + 8;
#pragma unroll
    for (int j = 0; j < 4; j++) {
        int n0 = nq * 32 + j * 8 + tg * 2;
        float b0 = __ldg(bias + n0), b1 = __ldg(bias + n0 + 1);
        if (r0 < NN) {
            float2 o;
            o.x = fmaxf(acc[j][0] + b0, 0.f);
            o.y = fmaxf(acc[j][1] + b1, 0.f);
            *(float2*)&out[(size_t)r0 * HH + n0] = o;
        }
        if (r1 < NN) {
            float2 o;
            o.x = fmaxf(acc[j][2] + b0, 0.f);
            o.y = fmaxf(acc[j][3] + b1, 0.f);
            *(float2*)&out[(size_t)r1 * HH + n0] = o;
        }
    }
}

// ---------------- host ----------------
extern "C" void kernel_launch(void* const* d_in, const int* in_sizes, int n_in,
                              void* d_out, int out_size) {
    const float* x = (const float*)d_in[0];
    const int* ei = (const int*)d_in[1];
    const float* Wl = (const float*)d_in[2];
    const float* bl = (const float*)d_in[3];
    const float* Wr = (const float*)d_in[4];
    float* out = (float*)d_out;
    (void)in_sizes; (void)n_in; (void)out_size;

    // ---- derive all JAX subkeys on host (partitionable semantics) ----
    unsigned kp[RR][2], kn[RR][2], s1k[RR][2], s2k[RR][2];
    for (int r = 0; r < RR; r++) {
        unsigned f0, f1;
        tf2x32(0u, 42u, 0u, (unsigned)r, f0, f1);           // fold_in
        tf2x32(f0, f1, 0u, 0u, kp[r][0], kp[r][1]);         // split[0]
        tf2x32(f0, f1, 0u, 1u, kn[r][0], kn[r][1]);         // split[1]
        unsigned pk0, pk1;
        tf2x32(f0, f1, 0u, 2u, pk0, pk1);                   // split[2] = kperm
        unsigned key10, key11;
        tf2x32(pk0, pk1, 0u, 0u, key10, key11);             // round1 new key
        tf2x32(pk0, pk1, 0u, 1u, s1k[r][0], s1k[r][1]);     // round1 use key
        tf2x32(key10, key11, 0u, 1u, s2k[r][0], s2k[r][1]); // round2 use key
    }

    cudaFuncSetAttribute(agg_gemm_kernel, cudaFuncAttributeMaxDynamicSharedMemorySize,
                         SMEM_ELEMS * 2);

    Keys12 KK;
    DropKeys DK;
    for (int r = 0; r < RR; r++) {
        KK.k[0 + 2 * r] = s1k[r][0]; KK.k[0 + 2 * r + 1] = s1k[r][1];
        KK.k[6 + 2 * r] = s2k[r][0]; KK.k[6 + 2 * r + 1] = s2k[r][1];
        DK.k[r * 4 + 0] = kp[r][0]; DK.k[r * 4 + 1] = kp[r][1];
        DK.k[r * 4 + 2] = kn[r][0]; DK.k[r * 4 + 3] = kn[r][1];
    }

    // ---- fork a side stream for the perm+dropout chain (graph-capture fork) ----
    cudaStream_t s1;
    cudaStreamCreateWithFlags(&s1, cudaStreamNonBlocking);
    cudaEvent_t evF, evJ;
    cudaEventCreateWithFlags(&evF, cudaEventDisableTiming);
    cudaEventCreateWithFlags(&evJ, cudaEventDisableTiming);
    cudaEventRecord(evF, 0);
    cudaStreamWaitEvent(s1, evF, 0);

    // ---- side stream: permutations + dropout ----
    dim3 eg((NN + 255) / 256, RR, 2);
    bzero_kernel<<<(2 * RR * NBKT + 255) / 256, 256, 0, s1>>>();
    keyhist_kernel<<<eg, 256, 0, s1>>>(KK);
    bprefix_kernel<<<dim3(RR, 2), NBKT, 0, s1>>>();
    bscatter_kernel<<<eg, 256, 0, s1>>>();
    brank_kernel<<<(2 * RR * NBKT * 32 + 255) / 256, 256, 0, s1>>>();
    dim3 cg((NN + 255) / 256, RR);
    compose_invperm_kernel<<<cg, 256, 0, s1>>>();
    dim3 dg((NN * 32 + 255) / 256, 1, RR);
    dropall_kernel<<<dg, 256, 0, s1>>>(x, DK);

    // ---- default stream: W pre-convert + CSR build ----
    wconv_kernel<<<(RR * 128 * 256 + 255) / 256, 256>>>(Wl, Wr);
    const int NB = (NN + 1023) / 1024;  // 49
    csr_zero<<<(RR * NN + 255) / 256, 256>>>();
    csr_hist<<<(RR * EE + 255) / 256, 256>>>(ei);
    scan1<<<dim3(NB, RR), 1024>>>();
    scan2<<<RR, 32>>>(NB);
    scan3<<<dim3(NB, RR), 1024>>>();
    csr_fill<<<(RR * EE + 255) / 256, 256>>>(ei);

    // ---- join, then all 6 fused agg+GEMM passes in ONE launch ----
    cudaEventRecord(evJ, s1);
    cudaStreamWaitEvent(0, evJ, 0);
    const int gemmBlocks = (NN + 63) / 64;   // 782
    agg_gemm_kernel<<<dim3(gemmBlocks, 2 * RR), 512, SMEM_ELEMS * 2>>>(bl, out);
}